// round 1
// baseline (speedup 1.0000x reference)
#include <cuda_runtime.h>
#include <cstdint>

#define NN 131072
#define ND 128
#define DD 128
#define LL 16
#define PP 8192
#define KK 8
#define PKE (PP*KK)          // 65536 edges per level
#define LEVE (LL-1)          // 15

// ---------------- scratch (static device globals; no allocation) ----------------
__device__ float g_h[(size_t)NN*DD];      // node-transform output == residual y
__device__ float g_hid[(size_t)NN*ND];    // hidden layer of node transform
__device__ float g_Mf[PP*DD];             // forward per-node message
__device__ float g_Mb[PP*DD];             // reverse per-node message
__device__ int   g_cnt[LEVE*PP];
__device__ int   g_rp[LEVE*(PP+1)];
__device__ int   g_fill[LEVE*PP];
__device__ int   g_col[LEVE*PKE];

// ---------------- f32x2 helpers ----------------
__device__ __forceinline__ unsigned long long pk2(float lo, float hi) {
    unsigned long long r;
    unsigned a = __float_as_uint(lo), b = __float_as_uint(hi);
    asm("mov.b64 %0, {%1, %2};" : "=l"(r) : "r"(a), "r"(b));
    return r;
}
__device__ __forceinline__ unsigned long long dup2f(float x) {
    unsigned long long r;
    unsigned a = __float_as_uint(x);
    asm("mov.b64 %0, {%1, %1};" : "=l"(r) : "r"(a));
    return r;
}
__device__ __forceinline__ void upk2(unsigned long long u, float& lo, float& hi) {
    unsigned a, b;
    asm("mov.b64 {%0, %1}, %2;" : "=r"(a), "=r"(b) : "l"(u));
    lo = __uint_as_float(a); hi = __uint_as_float(b);
}
__device__ __forceinline__ void ffma2(unsigned long long& acc, unsigned long long a, unsigned long long b) {
    asm("fma.rn.f32x2 %0, %1, %2, %0;" : "+l"(acc) : "l"(a), "l"(b));
}

// ---------------- GEMM: [rows,128] @ [128,128] + epilogue ----------------
// AMODE: 0 = direct rows (stride lda)
//        1 = gather-mean of KK=8 rows of A via gidx (forward MP)
//        2 = CSR gather-mean (reverse MP): rows cols[rp[gr]..rp[gr+1]) of A
// EPI:   0 = relu(acc + bias)
//        1 = acc + bias
//        2 = relu(acc + bias) + Res (Res stride = 128)
#define TILE_R 64
#define GT 128
#define ATP 68   // transposed-A pitch (floats): avoids 32-way store conflicts, keeps 8B align

template<int AMODE, int EPI>
__global__ __launch_bounds__(GT) void gemm128(
    const float* __restrict__ A, int lda,
    const int* __restrict__ gidx,
    const int* __restrict__ rp, const int* __restrict__ cols,
    const float* __restrict__ W, const float* __restrict__ bias,
    const float* __restrict__ Res,
    float* __restrict__ Out, int ldo, int rowsTotal)
{
    extern __shared__ float sm[];
    float* sW  = sm;                    // 128*128
    float* sAT = sm + 128*128;          // 128*ATP (A transposed: sAT[k][r])
    float* sB  = sAT + 128*ATP;         // 128
    const int tid  = threadIdx.x;
    const int row0 = blockIdx.x * TILE_R;

    // load W (row-major [k][c]) and bias
    {
        const float4* W4 = (const float4*)W;
        float4* sW4 = (float4*)sW;
        #pragma unroll
        for (int i = 0; i < 32; ++i) sW4[tid + GT*i] = W4[tid + GT*i];
        if (tid < 32) ((float4*)sB)[tid] = ((const float4*)bias)[tid];
    }
    // assemble transposed A tile
    for (int idx = tid; idx < TILE_R*32; idx += GT) {
        const int r  = idx >> 5;
        const int c4 = idx & 31;
        const int gr = row0 + r;
        float4 v = make_float4(0.f,0.f,0.f,0.f);
        if (gr < rowsTotal) {
            if (AMODE == 0) {
                v = *(const float4*)(A + (size_t)gr*lda + c4*4);
            } else if (AMODE == 1) {
                const int* s = gidx + gr*KK;
                #pragma unroll
                for (int k = 0; k < KK; ++k) {
                    const float4 t = *(const float4*)(A + (size_t)s[k]*DD + c4*4);
                    v.x += t.x; v.y += t.y; v.z += t.z; v.w += t.w;
                }
                v.x *= 0.125f; v.y *= 0.125f; v.z *= 0.125f; v.w *= 0.125f;
            } else {
                const int b0 = rp[gr], e0 = rp[gr+1];
                for (int j = b0; j < e0; ++j) {
                    const float4 t = *(const float4*)(A + (size_t)cols[j]*DD + c4*4);
                    v.x += t.x; v.y += t.y; v.z += t.z; v.w += t.w;
                }
                if (e0 > b0) {
                    const float inv = 1.0f/(float)(e0-b0);
                    v.x *= inv; v.y *= inv; v.z *= inv; v.w *= inv;
                }
            }
        }
        float* p = sAT + (c4*4)*ATP + r;
        p[0] = v.x; p[ATP] = v.y; p[2*ATP] = v.z; p[3*ATP] = v.w;
    }
    __syncthreads();

    const int tr = tid >> 4, tc = tid & 15;
    const int r0 = tr*8, c0 = tc*8;

    unsigned long long acc[4][8];
    #pragma unroll
    for (int i = 0; i < 4; ++i)
        #pragma unroll
        for (int j = 0; j < 8; ++j) acc[i][j] = 0ull;

    #pragma unroll 4
    for (int k = 0; k < 128; ++k) {
        unsigned long long pa[4];
        const float* arow = sAT + k*ATP + r0;
        pa[0] = *(const unsigned long long*)(arow + 0);
        pa[1] = *(const unsigned long long*)(arow + 2);
        pa[2] = *(const unsigned long long*)(arow + 4);
        pa[3] = *(const unsigned long long*)(arow + 6);
        const float4 w0 = *(const float4*)(sW + k*128 + c0);
        const float4 w1 = *(const float4*)(sW + k*128 + c0 + 4);
        unsigned long long wd[8];
        wd[0]=dup2f(w0.x); wd[1]=dup2f(w0.y); wd[2]=dup2f(w0.z); wd[3]=dup2f(w0.w);
        wd[4]=dup2f(w1.x); wd[5]=dup2f(w1.y); wd[6]=dup2f(w1.z); wd[7]=dup2f(w1.w);
        #pragma unroll
        for (int ip = 0; ip < 4; ++ip)
            #pragma unroll
            for (int j = 0; j < 8; ++j) ffma2(acc[ip][j], pa[ip], wd[j]);
    }

    float bv[8];
    {
        const float4 b0 = *(const float4*)(sB + c0);
        const float4 b1 = *(const float4*)(sB + c0 + 4);
        bv[0]=b0.x; bv[1]=b0.y; bv[2]=b0.z; bv[3]=b0.w;
        bv[4]=b1.x; bv[5]=b1.y; bv[6]=b1.z; bv[7]=b1.w;
    }
    #pragma unroll
    for (int i = 0; i < 8; ++i) {
        const int gr = row0 + r0 + i;
        if (gr >= rowsTotal) continue;
        float v[8];
        #pragma unroll
        for (int j = 0; j < 8; ++j) {
            float lo, hi; upk2(acc[i>>1][j], lo, hi);
            v[j] = ((i & 1) ? hi : lo) + bv[j];
        }
        if (EPI != 1) {
            #pragma unroll
            for (int j = 0; j < 8; ++j) v[j] = fmaxf(v[j], 0.f);
        }
        if (EPI == 2) {
            const float4 rA = *(const float4*)(Res + (size_t)gr*DD + c0);
            const float4 rB = *(const float4*)(Res + (size_t)gr*DD + c0 + 4);
            v[0]+=rA.x; v[1]+=rA.y; v[2]+=rA.z; v[3]+=rA.w;
            v[4]+=rB.x; v[5]+=rB.y; v[6]+=rB.z; v[7]+=rB.w;
        }
        float* o = Out + (size_t)gr*ldo + c0;
        *(float4*)o     = make_float4(v[0],v[1],v[2],v[3]);
        *(float4*)(o+4) = make_float4(v[4],v[5],v[6],v[7]);
    }
}

// ---------------- CSR build for reverse direction ----------------
__global__ void csr_count(const int* __restrict__ src, int* __restrict__ cnt) {
    const int tot = LEVE*PKE;
    for (int e = blockIdx.x*blockDim.x + threadIdx.x; e < tot; e += gridDim.x*blockDim.x) {
        const int lvl = e >> 16;             // PKE = 65536
        atomicAdd(&cnt[lvl*PP + src[e]], 1);
    }
}

__global__ void csr_scan(const int* __restrict__ cnt, int* __restrict__ rp, int* __restrict__ fill) {
    const int lvl = blockIdx.x;
    const int t = threadIdx.x;               // 256 threads, 32 entries each (P = 8192)
    const int base = lvl*PP;
    int c[32]; int sum = 0;
    #pragma unroll
    for (int j = 0; j < 32; ++j) { c[j] = cnt[base + t*32 + j]; sum += c[j]; }
    __shared__ int sh[256];
    sh[t] = sum; __syncthreads();
    for (int d = 1; d < 256; d <<= 1) {
        int v = (t >= d) ? sh[t-d] : 0;
        __syncthreads();
        sh[t] += v;
        __syncthreads();
    }
    int off = sh[t] - sum;                   // exclusive prefix
    int* rpl = rp + lvl*(PP+1);
    int* fl  = fill + base;
    #pragma unroll
    for (int j = 0; j < 32; ++j) { const int idx = t*32 + j; rpl[idx] = off; fl[idx] = off; off += c[j]; }
    if (t == 255) rpl[PP] = off;
}

__global__ void csr_fill(const int* __restrict__ src, int* __restrict__ fill, int* __restrict__ col) {
    const int tot = LEVE*PKE;
    for (int e = blockIdx.x*blockDim.x + threadIdx.x; e < tot; e += gridDim.x*blockDim.x) {
        const int lvl = e >> 16;
        const int le  = e & (PKE-1);
        const int pos = atomicAdd(&fill[lvl*PP + src[e]], 1);
        col[lvl*PKE + pos] = le >> 3;        // dst node of that edge = local_edge / K
    }
}

// ---------------- boundary levels: z = 0 -> y = relu(upd_b) + y_init ----------------
__global__ void init_ends(const float* __restrict__ fub, const float* __restrict__ bub,
                          float* __restrict__ Out) {
    const int idx = blockIdx.x*blockDim.x + threadIdx.x;
    if (idx >= PP*DD) return;
    const int p = idx >> 7, d = idx & 127;
    Out[(size_t)p*256 + d] = fmaxf(fub[d], 0.f) + g_h[(size_t)p*DD + d];
    const size_t n2 = (size_t)(LEVE*PP) + p;
    Out[n2*256 + 128 + d] = fmaxf(bub[d], 0.f) + g_h[n2*DD + d];
}

// ---------------- launch ----------------
extern "C" void kernel_launch(void* const* d_in, const int* in_sizes, int n_in,
                              void* d_out, int out_size) {
    const float* x       = (const float*)d_in[0];
    const int*   src     = (const int*)  d_in[1];
    const float* nt_w1   = (const float*)d_in[2];
    const float* nt_b1   = (const float*)d_in[3];
    const float* nt_w2   = (const float*)d_in[4];
    const float* nt_b2   = (const float*)d_in[5];
    const float* f_pre_w = (const float*)d_in[6];
    const float* f_pre_b = (const float*)d_in[7];
    const float* f_upd_w = (const float*)d_in[8];
    const float* f_upd_b = (const float*)d_in[9];
    const float* b_pre_w = (const float*)d_in[10];
    const float* b_pre_b = (const float*)d_in[11];
    const float* b_upd_w = (const float*)d_in[12];
    const float* b_upd_b = (const float*)d_in[13];
    float* out = (float*)d_out;   // [N, 256]: cols 0..127 forward, 128..255 reverse

    void *p_h, *p_hid, *p_Mf, *p_Mb, *p_cnt, *p_rp, *p_fill, *p_col;
    cudaGetSymbolAddress(&p_h,   g_h);
    cudaGetSymbolAddress(&p_hid, g_hid);
    cudaGetSymbolAddress(&p_Mf,  g_Mf);
    cudaGetSymbolAddress(&p_Mb,  g_Mb);
    cudaGetSymbolAddress(&p_cnt, g_cnt);
    cudaGetSymbolAddress(&p_rp,  g_rp);
    cudaGetSymbolAddress(&p_fill,g_fill);
    cudaGetSymbolAddress(&p_col, g_col);

    const int SMEM = (128*128 + 128*ATP + 128) * (int)sizeof(float);
    cudaFuncSetAttribute(gemm128<0,0>, cudaFuncAttributeMaxDynamicSharedMemorySize, SMEM);
    cudaFuncSetAttribute(gemm128<0,1>, cudaFuncAttributeMaxDynamicSharedMemorySize, SMEM);
    cudaFuncSetAttribute(gemm128<1,2>, cudaFuncAttributeMaxDynamicSharedMemorySize, SMEM);
    cudaFuncSetAttribute(gemm128<2,2>, cudaFuncAttributeMaxDynamicSharedMemorySize, SMEM);

    float* h   = (float*)p_h;
    float* hid = (float*)p_hid;
    float* Mf  = (float*)p_Mf;
    float* Mb  = (float*)p_Mb;
    int*   cnt = (int*)p_cnt;
    int*   rp  = (int*)p_rp;
    int*   fil = (int*)p_fill;
    int*   col = (int*)p_col;

    // 1) reverse-adjacency CSR (rebuilt deterministically each call)
    cudaMemsetAsync(p_cnt, 0, (size_t)LEVE*PP*sizeof(int));
    csr_count<<<512, 256>>>(src, cnt);
    csr_scan <<<LEVE, 256>>>(cnt, rp, fil);
    csr_fill <<<512, 256>>>(src, fil, col);

    // 2) node transform: h = relu(x@W1+b1)@W2 + b2
    gemm128<0,0><<<NN/TILE_R, GT, SMEM>>>(x,   ND, nullptr, nullptr, nullptr,
                                          nt_w1, nt_b1, nullptr, hid, DD, NN);
    gemm128<0,1><<<NN/TILE_R, GT, SMEM>>>(hid, DD, nullptr, nullptr, nullptr,
                                          nt_w2, nt_b2, nullptr, h,   DD, NN);

    // 3) boundary levels
    init_ends<<<(PP*DD + 255)/256, 256>>>(f_upd_b, b_upd_b, out);

    // 4) forward message passing (levels 1..15)
    for (int l = 1; l < LL; ++l) {
        gemm128<0,0><<<PP/TILE_R, GT, SMEM>>>(
            out + (size_t)(l-1)*PP*256, 256, nullptr, nullptr, nullptr,
            f_pre_w, f_pre_b, nullptr, Mf, DD, PP);
        gemm128<1,2><<<PP/TILE_R, GT, SMEM>>>(
            Mf, DD, src + (size_t)(l-1)*PKE, nullptr, nullptr,
            f_upd_w, f_upd_b, h + (size_t)l*PP*DD,
            out + (size_t)l*PP*256, 256, PP);
    }

    // 5) reverse message passing (levels 14..0)
    for (int l = LEVE-1; l >= 0; --l) {
        gemm128<0,0><<<PP/TILE_R, GT, SMEM>>>(
            out + (size_t)(l+1)*PP*256 + 128, 256, nullptr, nullptr, nullptr,
            b_pre_w, b_pre_b, nullptr, Mb, DD, PP);
        gemm128<2,2><<<PP/TILE_R, GT, SMEM>>>(
            Mb, DD, nullptr, rp + (size_t)l*(PP+1), col + (size_t)l*PKE,
            b_upd_w, b_upd_b, h + (size_t)l*PP*DD,
            out + (size_t)l*PP*256 + 128, 256, PP);
    }
}

// round 2
// speedup vs baseline: 1.6007x; 1.6007x over previous
#include <cuda_runtime.h>
#include <cstdint>

#define NN 131072
#define ND 128
#define DD 128
#define LL 16
#define PP 8192
#define KK 8
#define PKE (PP*KK)
#define LEVE (LL-1)

// ---------------- scratch (static device globals; no allocation) ----------------
__device__ float g_h[(size_t)NN*DD];
__device__ float g_hid[(size_t)NN*ND];
__device__ float g_Mf[PP*DD];
__device__ float g_Mb[PP*DD];
__device__ int   g_cnt[LEVE*PP];
__device__ int   g_rp[LEVE*(PP+1)];
__device__ int   g_fill[LEVE*PP];
__device__ int   g_col[LEVE*PKE];

// ---------------- tf32 helpers ----------------
__device__ __forceinline__ unsigned tf32c(float f) {
    unsigned r;
    asm("cvt.rna.tf32.f32 %0, %1;" : "=r"(r) : "f"(f));
    return r;
}
__device__ __forceinline__ uint4 tf32c4(float4 v) {
    uint4 r;
    r.x = tf32c(v.x); r.y = tf32c(v.y); r.z = tf32c(v.z); r.w = tf32c(v.w);
    return r;
}
__device__ __forceinline__ void mma8(float* d, const unsigned* a, const unsigned* b) {
    asm("mma.sync.aligned.m16n8k8.row.col.f32.tf32.tf32.f32 "
        "{%0,%1,%2,%3},{%4,%5,%6,%7},{%8,%9},{%0,%1,%2,%3};"
        : "+f"(d[0]), "+f"(d[1]), "+f"(d[2]), "+f"(d[3])
        : "r"(a[0]), "r"(a[1]), "r"(a[2]), "r"(a[3]), "r"(b[0]), "r"(b[1]));
}

// ---------------- tf32 tensor-core GEMM: [rows,128] @ [128,128] + epilogue ----------------
// AMODE: 0 direct rows (stride lda) | 1 gather-mean KK rows via gidx | 2 CSR gather-mean
// EPI:   0 relu(acc+b) | 1 acc+b | 2 relu(acc+b)+Res (Res stride 128)
#define TILE_R 64
#define GT 128
#define AP 132   // A smem pitch in floats (mod 32 == 4 -> conflict-free frags)
#define WP 136   // W smem pitch in floats (mod 32 == 8 -> conflict-free frags)
#define SMEM_B ((TILE_R*AP + 128*WP + 128) * 4)

template<int AMODE, int EPI>
__global__ __launch_bounds__(GT) void tgemm(
    const float* __restrict__ A, int lda,
    const int* __restrict__ gidx,
    const int* __restrict__ rp, const int* __restrict__ cols,
    const float* __restrict__ W, const float* __restrict__ bias,
    const float* __restrict__ Res,
    float* __restrict__ Out, int ldo, int rowsTotal)
{
    extern __shared__ unsigned sm[];
    unsigned* sA = sm;                      // [64][AP]  tf32 bits
    unsigned* sW = sm + TILE_R*AP;          // [128][WP] tf32 bits
    float*    sB = (float*)(sm + TILE_R*AP + 128*WP);  // 128 bias floats
    const int tid  = threadIdx.x;
    const int row0 = blockIdx.x * TILE_R;

    // ---- load W [k][c] row-major, convert to tf32, STS.128 ----
    {
        const float4* W4 = (const float4*)W;
        uint4* sW4 = (uint4*)sW;            // pitch WP/4 = 34
        #pragma unroll
        for (int i = 0; i < 32; ++i) {
            const int idx = tid + GT*i;     // 4096 float4
            const int k = idx >> 5, c4 = idx & 31;
            sW4[k*34 + c4] = tf32c4(W4[idx]);
        }
        if (tid < 32) ((float4*)sB)[tid] = ((const float4*)bias)[tid];
    }
    // ---- assemble A tile (fp32 math for means, then tf32) ----
    {
        uint4* sA4 = (uint4*)sA;            // pitch AP/4 = 33
        #pragma unroll
        for (int it = 0; it < 16; ++it) {
            const int idx = tid + GT*it;    // 2048 float4 slots
            const int r = idx >> 5, c4 = idx & 31;
            const int gr = row0 + r;
            float4 v = make_float4(0.f, 0.f, 0.f, 0.f);
            if (gr < rowsTotal) {
                if (AMODE == 0) {
                    v = *(const float4*)(A + (size_t)gr*lda + c4*4);
                } else if (AMODE == 1) {
                    const int* s = gidx + gr*KK;
                    #pragma unroll
                    for (int k = 0; k < KK; ++k) {
                        const float4 t = *(const float4*)(A + (size_t)s[k]*DD + c4*4);
                        v.x += t.x; v.y += t.y; v.z += t.z; v.w += t.w;
                    }
                    v.x *= 0.125f; v.y *= 0.125f; v.z *= 0.125f; v.w *= 0.125f;
                } else {
                    const int b0 = rp[gr], e0 = rp[gr+1];
                    for (int j = b0; j < e0; ++j) {
                        const float4 t = *(const float4*)(A + (size_t)cols[j]*DD + c4*4);
                        v.x += t.x; v.y += t.y; v.z += t.z; v.w += t.w;
                    }
                    if (e0 > b0) {
                        const float inv = 1.0f/(float)(e0-b0);
                        v.x *= inv; v.y *= inv; v.z *= inv; v.w *= inv;
                    }
                }
            }
            sA4[r*33 + c4] = tf32c4(v);
        }
    }
    __syncthreads();

    // ---- warp tiling: 4 warps, 2(m) x 2(n); warp tile 32 rows x 64 cols ----
    const int w = tid >> 5, lane = tid & 31;
    const int g = lane >> 2, t = lane & 3;
    const int wr = w & 1, wc = w >> 1;

    float acc[2][8][4];
    #pragma unroll
    for (int i = 0; i < 2; ++i)
        #pragma unroll
        for (int j = 0; j < 8; ++j)
            #pragma unroll
            for (int q = 0; q < 4; ++q) acc[i][j][q] = 0.f;

    #pragma unroll
    for (int ks = 0; ks < 16; ++ks) {
        const int k0 = ks * 8;
        unsigned a[2][4];
        #pragma unroll
        for (int i = 0; i < 2; ++i) {
            const unsigned* ap = sA + (wr*32 + i*16 + g)*AP + k0 + t;
            a[i][0] = ap[0];
            a[i][1] = ap[8*AP];
            a[i][2] = ap[4];
            a[i][3] = ap[8*AP + 4];
        }
        unsigned b[8][2];
        #pragma unroll
        for (int j = 0; j < 8; ++j) {
            const unsigned* bp = sW + (k0 + t)*WP + wc*64 + j*8 + g;
            b[j][0] = bp[0];
            b[j][1] = bp[4*WP];
        }
        #pragma unroll
        for (int i = 0; i < 2; ++i)
            #pragma unroll
            for (int j = 0; j < 8; ++j)
                mma8(acc[i][j], a[i], b[j]);
    }

    // ---- epilogue ----
    #pragma unroll
    for (int i = 0; i < 2; ++i) {
        const int r_lo = row0 + wr*32 + i*16 + g;
        const int r_hi = r_lo + 8;
        #pragma unroll
        for (int j = 0; j < 8; ++j) {
            const int col = wc*64 + j*8 + 2*t;
            const float b0 = sB[col], b1 = sB[col+1];
            float v0 = acc[i][j][0] + b0, v1 = acc[i][j][1] + b1;
            float v2 = acc[i][j][2] + b0, v3 = acc[i][j][3] + b1;
            if (EPI != 1) {
                v0 = fmaxf(v0, 0.f); v1 = fmaxf(v1, 0.f);
                v2 = fmaxf(v2, 0.f); v3 = fmaxf(v3, 0.f);
            }
            if (EPI == 2) {
                const float2 rl = *(const float2*)(Res + (size_t)r_lo*DD + col);
                const float2 rh = *(const float2*)(Res + (size_t)r_hi*DD + col);
                v0 += rl.x; v1 += rl.y; v2 += rh.x; v3 += rh.y;
            }
            if (r_lo < rowsTotal) *(float2*)(Out + (size_t)r_lo*ldo + col) = make_float2(v0, v1);
            if (r_hi < rowsTotal) *(float2*)(Out + (size_t)r_hi*ldo + col) = make_float2(v2, v3);
        }
    }
}

// ---------------- CSR build for reverse direction ----------------
__global__ void csr_count(const int* __restrict__ src, int* __restrict__ cnt) {
    const int tot = LEVE*PKE;
    for (int e = blockIdx.x*blockDim.x + threadIdx.x; e < tot; e += gridDim.x*blockDim.x) {
        const int lvl = e >> 16;
        atomicAdd(&cnt[lvl*PP + src[e]], 1);
    }
}

__global__ void csr_scan(const int* __restrict__ cnt, int* __restrict__ rp, int* __restrict__ fill) {
    const int lvl = blockIdx.x;
    const int t = threadIdx.x;
    const int base = lvl*PP;
    int c[32]; int sum = 0;
    #pragma unroll
    for (int j = 0; j < 32; ++j) { c[j] = cnt[base + t*32 + j]; sum += c[j]; }
    __shared__ int sh[256];
    sh[t] = sum; __syncthreads();
    for (int d = 1; d < 256; d <<= 1) {
        int v = (t >= d) ? sh[t-d] : 0;
        __syncthreads();
        sh[t] += v;
        __syncthreads();
    }
    int off = sh[t] - sum;
    int* rpl = rp + lvl*(PP+1);
    int* fl  = fill + base;
    #pragma unroll
    for (int j = 0; j < 32; ++j) { const int idx = t*32 + j; rpl[idx] = off; fl[idx] = off; off += c[j]; }
    if (t == 255) rpl[PP] = off;
}

__global__ void csr_fill(const int* __restrict__ src, int* __restrict__ fill, int* __restrict__ col) {
    const int tot = LEVE*PKE;
    for (int e = blockIdx.x*blockDim.x + threadIdx.x; e < tot; e += gridDim.x*blockDim.x) {
        const int lvl = e >> 16;
        const int le  = e & (PKE-1);
        const int pos = atomicAdd(&fill[lvl*PP + src[e]], 1);
        col[lvl*PKE + pos] = le >> 3;
    }
}

// ---------------- boundary levels ----------------
__global__ void init_ends(const float* __restrict__ fub, const float* __restrict__ bub,
                          float* __restrict__ Out) {
    const int idx = blockIdx.x*blockDim.x + threadIdx.x;
    if (idx >= PP*DD) return;
    const int p = idx >> 7, d = idx & 127;
    Out[(size_t)p*256 + d] = fmaxf(fub[d], 0.f) + g_h[(size_t)p*DD + d];
    const size_t n2 = (size_t)(LEVE*PP) + p;
    Out[n2*256 + 128 + d] = fmaxf(bub[d], 0.f) + g_h[n2*DD + d];
}

// ---------------- launch ----------------
extern "C" void kernel_launch(void* const* d_in, const int* in_sizes, int n_in,
                              void* d_out, int out_size) {
    const float* x       = (const float*)d_in[0];
    const int*   src     = (const int*)  d_in[1];
    const float* nt_w1   = (const float*)d_in[2];
    const float* nt_b1   = (const float*)d_in[3];
    const float* nt_w2   = (const float*)d_in[4];
    const float* nt_b2   = (const float*)d_in[5];
    const float* f_pre_w = (const float*)d_in[6];
    const float* f_pre_b = (const float*)d_in[7];
    const float* f_upd_w = (const float*)d_in[8];
    const float* f_upd_b = (const float*)d_in[9];
    const float* b_pre_w = (const float*)d_in[10];
    const float* b_pre_b = (const float*)d_in[11];
    const float* b_upd_w = (const float*)d_in[12];
    const float* b_upd_b = (const float*)d_in[13];
    float* out = (float*)d_out;   // [N, 256]

    void *p_h, *p_hid, *p_Mf, *p_Mb, *p_cnt, *p_rp, *p_fill, *p_col;
    cudaGetSymbolAddress(&p_h,   g_h);
    cudaGetSymbolAddress(&p_hid, g_hid);
    cudaGetSymbolAddress(&p_Mf,  g_Mf);
    cudaGetSymbolAddress(&p_Mb,  g_Mb);
    cudaGetSymbolAddress(&p_cnt, g_cnt);
    cudaGetSymbolAddress(&p_rp,  g_rp);
    cudaGetSymbolAddress(&p_fill,g_fill);
    cudaGetSymbolAddress(&p_col, g_col);

    cudaFuncSetAttribute(tgemm<0,0>, cudaFuncAttributeMaxDynamicSharedMemorySize, SMEM_B);
    cudaFuncSetAttribute(tgemm<0,1>, cudaFuncAttributeMaxDynamicSharedMemorySize, SMEM_B);
    cudaFuncSetAttribute(tgemm<1,2>, cudaFuncAttributeMaxDynamicSharedMemorySize, SMEM_B);
    cudaFuncSetAttribute(tgemm<2,2>, cudaFuncAttributeMaxDynamicSharedMemorySize, SMEM_B);

    float* h   = (float*)p_h;
    float* hid = (float*)p_hid;
    float* Mf  = (float*)p_Mf;
    float* Mb  = (float*)p_Mb;
    int*   cnt = (int*)p_cnt;
    int*   rp  = (int*)p_rp;
    int*   fil = (int*)p_fill;
    int*   col = (int*)p_col;

    // 1) reverse-adjacency CSR
    cudaMemsetAsync(p_cnt, 0, (size_t)LEVE*PP*sizeof(int));
    csr_count<<<512, 256>>>(src, cnt);
    csr_scan <<<LEVE, 256>>>(cnt, rp, fil);
    csr_fill <<<512, 256>>>(src, fil, col);

    // 2) node transform
    tgemm<0,0><<<NN/TILE_R, GT, SMEM_B>>>(x,   ND, nullptr, nullptr, nullptr,
                                          nt_w1, nt_b1, nullptr, hid, DD, NN);
    tgemm<0,1><<<NN/TILE_R, GT, SMEM_B>>>(hid, DD, nullptr, nullptr, nullptr,
                                          nt_w2, nt_b2, nullptr, h,   DD, NN);

    // 3) boundary levels
    init_ends<<<(PP*DD + 255)/256, 256>>>(f_upd_b, b_upd_b, out);

    // 4) forward message passing
    for (int l = 1; l < LL; ++l) {
        tgemm<0,0><<<PP/TILE_R, GT, SMEM_B>>>(
            out + (size_t)(l-1)*PP*256, 256, nullptr, nullptr, nullptr,
            f_pre_w, f_pre_b, nullptr, Mf, DD, PP);
        tgemm<1,2><<<PP/TILE_R, GT, SMEM_B>>>(
            Mf, DD, src + (size_t)(l-1)*PKE, nullptr, nullptr,
            f_upd_w, f_upd_b, h + (size_t)l*PP*DD,
            out + (size_t)l*PP*256, 256, PP);
    }

    // 5) reverse message passing
    for (int l = LEVE-1; l >= 0; --l) {
        tgemm<0,0><<<PP/TILE_R, GT, SMEM_B>>>(
            out + (size_t)(l+1)*PP*256 + 128, 256, nullptr, nullptr, nullptr,
            b_pre_w, b_pre_b, nullptr, Mb, DD, PP);
        tgemm<2,2><<<PP/TILE_R, GT, SMEM_B>>>(
            Mb, DD, nullptr, rp + (size_t)l*(PP+1), col + (size_t)l*PKE,
            b_upd_w, b_upd_b, h + (size_t)l*PP*DD,
            out + (size_t)l*PP*256 + 128, 256, PP);
    }
}

// round 4
// speedup vs baseline: 2.1969x; 1.3725x over previous
#include <cuda_runtime.h>
#include <cstdint>

#define NN 131072
#define DD 128
#define LL 16
#define PP 8192
#define KK 8
#define PKE (PP*KK)
#define LEVE (LL-1)
#define CH 64            // CTAs per chain

// ---------------- scratch (static device globals; no allocation) ----------------
__device__ float g_h[(size_t)NN*DD];
__device__ float g_hid[(size_t)NN*DD];
__device__ float g_Mf[2*PP*DD];
__device__ float g_Mb[2*PP*DD];
__device__ int   g_cnt[LEVE*PP];
__device__ int   g_rp[LEVE*(PP+1)];
__device__ int   g_fill[LEVE*PP];
__device__ int   g_col[LEVE*PKE];
__device__ unsigned g_bars[2];

// ---------------- tf32 / mma helpers ----------------
__device__ __forceinline__ unsigned tf32c(float f) {
    unsigned r;
    asm("cvt.rna.tf32.f32 %0, %1;" : "=r"(r) : "f"(f));
    return r;
}
__device__ __forceinline__ void mma8(float* d, const unsigned* a, const unsigned* b) {
    asm("mma.sync.aligned.m16n8k8.row.col.f32.tf32.tf32.f32 "
        "{%0,%1,%2,%3},{%4,%5,%6,%7},{%8,%9},{%0,%1,%2,%3};"
        : "+f"(d[0]), "+f"(d[1]), "+f"(d[2]), "+f"(d[3])
        : "r"(a[0]), "r"(a[1]), "r"(a[2]), "r"(a[3]), "r"(b[0]), "r"(b[1]));
}

// ---------------- fragment-ready smem layouts ----------------
// A tile: 64 rows x 128 k. Blocks (mb in [0,4), kb in [0,16)), 132-unsigned pitch.
// slot(r,k) = (r&7)*16 + (k&3)*4 + ((k>>2)&1)*2 + ((r>>3)&1)
#define A_FRAG_SZ (4*16*132)          // 8448
// W: 128 k x 128 cols. Blocks (cb in [0,16), kb in [0,16)), 66-unsigned pitch.
// slot(k,nc) = nc*8 + (k&3)*2 + ((k>>2)&1),  nc = c&7
#define W_FRAG_SZ (16*16*66)          // 16896

__device__ __forceinline__ void frag_storeA(unsigned* sA, int r, int c4, float4 v) {
    unsigned* p = sA + (((r>>4)*16 + (c4>>1))*132) + ((r&7)*16) + ((c4&1)*2) + ((r&15)>>3);
    p[0] = tf32c(v.x); p[4] = tf32c(v.y); p[8] = tf32c(v.z); p[12] = tf32c(v.w);
}
__device__ __forceinline__ void frag_storeW(unsigned* sW, int k, int c4, float4 v) {
    // base nc = (c4&1)*4, nc stride = 8 slots
    unsigned* p = sW + (((c4>>1)*16 + (k>>3))*66) + ((c4&1)*32) + ((k&3)*2) + ((k>>2)&1);
    p[0] = tf32c(v.x); p[8] = tf32c(v.y); p[16] = tf32c(v.z); p[24] = tf32c(v.w);
}

// ---------------- GEMM core: 64x128 tile, 8 warps (wm in [0,2), wn in [0,4)) ----------------
__device__ __forceinline__ void gemm_core(const unsigned* __restrict__ sA,
                                          const unsigned* __restrict__ sW,
                                          int wm, int wn, int lane,
                                          float acc[2][4][4]) {
    #pragma unroll
    for (int i = 0; i < 2; ++i)
        #pragma unroll
        for (int j = 0; j < 4; ++j)
            #pragma unroll
            for (int q = 0; q < 4; ++q) acc[i][j][q] = 0.f;
    #pragma unroll
    for (int kb = 0; kb < 16; ++kb) {
        unsigned a[2][4];
        #pragma unroll
        for (int i = 0; i < 2; ++i) {
            const uint4 v = *(const uint4*)(sA + (((wm*2+i)*16 + kb)*132) + lane*4);
            a[i][0] = v.x; a[i][1] = v.y; a[i][2] = v.z; a[i][3] = v.w;
        }
        unsigned b[4][2];
        #pragma unroll
        for (int j = 0; j < 4; ++j) {
            const uint2 v = *(const uint2*)(sW + (((wn*4+j)*16 + kb)*66) + lane*2);
            b[j][0] = v.x; b[j][1] = v.y;
        }
        #pragma unroll
        for (int i = 0; i < 2; ++i)
            #pragma unroll
            for (int j = 0; j < 4; ++j)
                mma8(acc[i][j], a[i], b[j]);
    }
}

// ---------------- node transform GEMM ----------------
#define NT_SMEM ((W_FRAG_SZ + A_FRAG_SZ + 128) * 4)

template<int EPI>
__global__ __launch_bounds__(256, 2) void ntgemm(
    const float* __restrict__ A, const float* __restrict__ W,
    const float* __restrict__ bias, float* __restrict__ Out)
{
    extern __shared__ unsigned sm[];
    unsigned* sW = sm;
    unsigned* sA = sm + W_FRAG_SZ;
    float*    sB = (float*)(sm + W_FRAG_SZ + A_FRAG_SZ);
    const int tid = threadIdx.x, lane = tid & 31, w = tid >> 5;
    const int wm = w >> 2, wn = w & 3;
    const int g = lane >> 2, t = lane & 3;
    const int r0 = blockIdx.x * 128;

    #pragma unroll
    for (int it = 0; it < 16; ++it) {
        const int idx = tid + 256*it;
        frag_storeW(sW, idx >> 5, idx & 31, ((const float4*)W)[idx]);
    }
    if (tid < 32) ((float4*)sB)[tid] = ((const float4*)bias)[tid];
    __syncthreads();

    for (int sub = 0; sub < 2; ++sub) {
        #pragma unroll
        for (int it = 0; it < 8; ++it) {
            const int idx = tid + 256*it;
            const int r = idx >> 5, c4 = idx & 31;
            frag_storeA(sA, r, c4,
                *(const float4*)(A + (size_t)(r0 + sub*64 + r)*128 + c4*4));
        }
        __syncthreads();
        float acc[2][4][4];
        gemm_core(sA, sW, wm, wn, lane, acc);
        #pragma unroll
        for (int i = 0; i < 2; ++i) {
            const int rl = r0 + sub*64 + wm*32 + i*16 + g;
            #pragma unroll
            for (int j = 0; j < 4; ++j) {
                const int c = wn*32 + j*8 + t*2;
                const float b0 = sB[c], b1 = sB[c+1];
                float v0 = acc[i][j][0]+b0, v1 = acc[i][j][1]+b1;
                float v2 = acc[i][j][2]+b0, v3 = acc[i][j][3]+b1;
                if (EPI == 0) {
                    v0 = fmaxf(v0,0.f); v1 = fmaxf(v1,0.f);
                    v2 = fmaxf(v2,0.f); v3 = fmaxf(v3,0.f);
                }
                *(float2*)(Out + (size_t)rl*128 + c)     = make_float2(v0,v1);
                *(float2*)(Out + (size_t)(rl+8)*128 + c) = make_float2(v2,v3);
            }
        }
        __syncthreads();
    }
}

// ---------------- grid sync (release/acquire by all threads) ----------------
__device__ __forceinline__ void gsync(unsigned* ctr, unsigned tgt) {
    __syncthreads();
    __threadfence();                       // release: all threads' prior writes
    if (threadIdx.x == 0) {
        atomicAdd(ctr, 1u);
        while (*(volatile unsigned*)ctr < tgt) __nanosleep(64);
    }
    __syncthreads();
    __threadfence();                       // acquire: subsequent reads see fresh data
}

// ---------------- persistent dual-chain message-passing kernel ----------------
#define CH_SMEM ((2*W_FRAG_SZ + A_FRAG_SZ + 256) * 4)

__global__ __launch_bounds__(256, 1) void chain_kernel(
    float* __restrict__ out,
    const int* __restrict__ src,
    const float* __restrict__ f_pre_w, const float* __restrict__ f_pre_b,
    const float* __restrict__ f_upd_w, const float* __restrict__ f_upd_b,
    const float* __restrict__ b_pre_w, const float* __restrict__ b_pre_b,
    const float* __restrict__ b_upd_w, const float* __restrict__ b_upd_b)
{
    extern __shared__ unsigned sm[];
    unsigned* sWpre = sm;
    unsigned* sWupd = sm + W_FRAG_SZ;
    unsigned* sA    = sm + 2*W_FRAG_SZ;
    float*    sB    = (float*)(sm + 2*W_FRAG_SZ + A_FRAG_SZ);  // [0,128) pre_b, [128,256) upd_b

    const int tid = threadIdx.x, lane = tid & 31, w = tid >> 5;
    const int wm = w >> 2, wn = w & 3;
    const int g = lane >> 2, t = lane & 3;
    const bool fwd = blockIdx.x < CH;
    const int cc = fwd ? blockIdx.x : blockIdx.x - CH;
    const int r0 = cc * 128;
    const int cofs = fwd ? 0 : 128;
    unsigned* ctr = &g_bars[fwd ? 0 : 1];
    float* Mbase = fwd ? g_Mf : g_Mb;
    const float* preW = fwd ? f_pre_w : b_pre_w;
    const float* preB = fwd ? f_pre_b : b_pre_b;
    const float* updW = fwd ? f_upd_w : b_upd_w;
    const float* updB = fwd ? f_upd_b : b_upd_b;

    #pragma unroll
    for (int it = 0; it < 16; ++it) {
        const int idx = tid + 256*it;
        frag_storeW(sWpre, idx >> 5, idx & 31, ((const float4*)preW)[idx]);
        frag_storeW(sWupd, idx >> 5, idx & 31, ((const float4*)updW)[idx]);
    }
    if (tid < 32) {
        ((float4*)sB)[tid]       = ((const float4*)preB)[tid];
        ((float4*)(sB+128))[tid] = ((const float4*)updB)[tid];
    }
    __syncthreads();

    // boundary level: y = relu(upd_b) + h
    {
        const int lvl0 = fwd ? 0 : LEVE;
        #pragma unroll
        for (int it = 0; it < 16; ++it) {
            const int idx = tid + 256*it;
            const int r = idx >> 5, c4 = idx & 31;
            const size_t node = (size_t)lvl0*PP + r0 + r;
            const float4 ub = *(const float4*)(sB + 128 + c4*4);
            const float4 hv = *(const float4*)(g_h + node*128 + c4*4);
            float4 o;
            o.x = fmaxf(ub.x,0.f)+hv.x; o.y = fmaxf(ub.y,0.f)+hv.y;
            o.z = fmaxf(ub.z,0.f)+hv.z; o.w = fmaxf(ub.w,0.f)+hv.w;
            *(float4*)(out + node*256 + cofs + c4*4) = o;
        }
    }
    __syncthreads();

    unsigned tgt = 0;
    for (int step = 0; step < LEVE; ++step) {
        const int l    = fwd ? (1+step) : (LEVE-1-step);
        const int ylvl = fwd ? (l-1)    : (l+1);
        float* Mbuf = Mbase + (size_t)(l & 1)*PP*DD;

        // ---- phase A: M[p] = relu(Y[ylvl][p] @ preW + preB), own 128 rows ----
        for (int sub = 0; sub < 2; ++sub) {
            #pragma unroll
            for (int it = 0; it < 8; ++it) {
                const int idx = tid + 256*it;
                const int r = idx >> 5, c4 = idx & 31;
                frag_storeA(sA, r, c4,
                    *(const float4*)(out + ((size_t)ylvl*PP + r0 + sub*64 + r)*256 + cofs + c4*4));
            }
            __syncthreads();
            float acc[2][4][4];
            gemm_core(sA, sWpre, wm, wn, lane, acc);
            #pragma unroll
            for (int i = 0; i < 2; ++i) {
                const int rl = r0 + sub*64 + wm*32 + i*16 + g;
                #pragma unroll
                for (int j = 0; j < 4; ++j) {
                    const int c = wn*32 + j*8 + t*2;
                    const float b0 = sB[c], b1 = sB[c+1];
                    const float v0 = fmaxf(acc[i][j][0]+b0, 0.f);
                    const float v1 = fmaxf(acc[i][j][1]+b1, 0.f);
                    const float v2 = fmaxf(acc[i][j][2]+b0, 0.f);
                    const float v3 = fmaxf(acc[i][j][3]+b1, 0.f);
                    *(float2*)(Mbuf + (size_t)rl*128 + c)     = make_float2(v0,v1);
                    *(float2*)(Mbuf + (size_t)(rl+8)*128 + c) = make_float2(v2,v3);
                }
            }
            __syncthreads();
        }

        // ---- chain-wide barrier: all M writes visible ----
        tgt += CH;
        gsync(ctr, tgt);

        // ---- phase B: z = gather-mean(M); Y[l] = relu(z @ updW + updB) + h ----
        for (int sub = 0; sub < 2; ++sub) {
            #pragma unroll 1
            for (int it = 0; it < 8; ++it) {
                const int idx = tid + 256*it;
                const int r = idx >> 5, c4 = idx & 31;
                const int pl = r0 + sub*64 + r;
                float4 v = make_float4(0.f,0.f,0.f,0.f);
                if (fwd) {
                    const int* s = src + (size_t)(l-1)*PKE + pl*KK;
                    #pragma unroll
                    for (int k = 0; k < KK; ++k) {
                        const float4 m = *(const float4*)(Mbuf + (size_t)s[k]*128 + c4*4);
                        v.x += m.x; v.y += m.y; v.z += m.z; v.w += m.w;
                    }
                    v.x *= 0.125f; v.y *= 0.125f; v.z *= 0.125f; v.w *= 0.125f;
                } else {
                    const int* rpl = g_rp + l*(PP+1);
                    const int b0 = rpl[pl], e0 = rpl[pl+1];
                    const int* colsl = g_col + (size_t)l*PKE;
                    for (int jj = b0; jj < e0; ++jj) {
                        const float4 m = *(const float4*)(Mbuf + (size_t)colsl[jj]*128 + c4*4);
                        v.x += m.x; v.y += m.y; v.z += m.z; v.w += m.w;
                    }
                    if (e0 > b0) {
                        const float inv = 1.0f/(float)(e0-b0);
                        v.x *= inv; v.y *= inv; v.z *= inv; v.w *= inv;
                    }
                }
                frag_storeA(sA, r, c4, v);
            }
            __syncthreads();
            float acc[2][4][4];
            gemm_core(sA, sWupd, wm, wn, lane, acc);
            #pragma unroll
            for (int i = 0; i < 2; ++i) {
                const int rl = r0 + sub*64 + wm*32 + i*16 + g;
                #pragma unroll
                for (int j = 0; j < 4; ++j) {
                    const int c = wn*32 + j*8 + t*2;
                    const float b0 = sB[128+c], b1 = sB[128+c+1];
                    float v0 = fmaxf(acc[i][j][0]+b0, 0.f);
                    float v1 = fmaxf(acc[i][j][1]+b1, 0.f);
                    float v2 = fmaxf(acc[i][j][2]+b0, 0.f);
                    float v3 = fmaxf(acc[i][j][3]+b1, 0.f);
                    const size_t nlo = (size_t)l*PP + rl, nhi = nlo + 8;
                    const float2 hlo = *(const float2*)(g_h + nlo*128 + c);
                    const float2 hhi = *(const float2*)(g_h + nhi*128 + c);
                    v0 += hlo.x; v1 += hlo.y; v2 += hhi.x; v3 += hhi.y;
                    *(float2*)(out + nlo*256 + cofs + c) = make_float2(v0,v1);
                    *(float2*)(out + nhi*256 + cofs + c) = make_float2(v2,v3);
                }
            }
            __syncthreads();
        }
    }
}

// ---------------- CSR build for reverse direction ----------------
__global__ void csr_count(const int* __restrict__ src, int* __restrict__ cnt) {
    const int tot = LEVE*PKE;
    for (int e = blockIdx.x*blockDim.x + threadIdx.x; e < tot; e += gridDim.x*blockDim.x)
        atomicAdd(&cnt[(e >> 16)*PP + src[e]], 1);
}
__global__ void csr_scan(const int* __restrict__ cnt, int* __restrict__ rp, int* __restrict__ fill) {
    const int lvl = blockIdx.x;
    const int t = threadIdx.x;
    const int base = lvl*PP;
    int c[32]; int sum = 0;
    #pragma unroll
    for (int j = 0; j < 32; ++j) { c[j] = cnt[base + t*32 + j]; sum += c[j]; }
    __shared__ int sh[256];
    sh[t] = sum; __syncthreads();
    for (int d = 1; d < 256; d <<= 1) {
        int v = (t >= d) ? sh[t-d] : 0;
        __syncthreads();
        sh[t] += v;
        __syncthreads();
    }
    int off = sh[t] - sum;
    int* rpl = rp + lvl*(PP+1);
    int* fl  = fill + base;
    #pragma unroll
    for (int j = 0; j < 32; ++j) { const int idx = t*32 + j; rpl[idx] = off; fl[idx] = off; off += c[j]; }
    if (t == 255) rpl[PP] = off;
}
__global__ void csr_fill(const int* __restrict__ src, int* __restrict__ fill, int* __restrict__ col) {
    const int tot = LEVE*PKE;
    for (int e = blockIdx.x*blockDim.x + threadIdx.x; e < tot; e += gridDim.x*blockDim.x) {
        const int lvl = e >> 16;
        const int le  = e & (PKE-1);
        const int pos = atomicAdd(&fill[lvl*PP + src[e]], 1);
        col[(size_t)lvl*PKE + pos] = le >> 3;
    }
}

// ---------------- launch ----------------
extern "C" void kernel_launch(void* const* d_in, const int* in_sizes, int n_in,
                              void* d_out, int out_size) {
    const float* x       = (const float*)d_in[0];
    const int*   src     = (const int*)  d_in[1];
    const float* nt_w1   = (const float*)d_in[2];
    const float* nt_b1   = (const float*)d_in[3];
    const float* nt_w2   = (const float*)d_in[4];
    const float* nt_b2   = (const float*)d_in[5];
    const float* f_pre_w = (const float*)d_in[6];
    const float* f_pre_b = (const float*)d_in[7];
    const float* f_upd_w = (const float*)d_in[8];
    const float* f_upd_b = (const float*)d_in[9];
    const float* b_pre_w = (const float*)d_in[10];
    const float* b_pre_b = (const float*)d_in[11];
    const float* b_upd_w = (const float*)d_in[12];
    const float* b_upd_b = (const float*)d_in[13];
    float* out = (float*)d_out;

    void *p_h, *p_hid, *p_cnt, *p_rp, *p_fill, *p_col, *p_bars;
    cudaGetSymbolAddress(&p_h,   g_h);
    cudaGetSymbolAddress(&p_hid, g_hid);
    cudaGetSymbolAddress(&p_cnt, g_cnt);
    cudaGetSymbolAddress(&p_rp,  g_rp);
    cudaGetSymbolAddress(&p_fill,g_fill);
    cudaGetSymbolAddress(&p_col, g_col);
    cudaGetSymbolAddress(&p_bars,g_bars);

    cudaFuncSetAttribute(ntgemm<0>,    cudaFuncAttributeMaxDynamicSharedMemorySize, NT_SMEM);
    cudaFuncSetAttribute(ntgemm<1>,    cudaFuncAttributeMaxDynamicSharedMemorySize, NT_SMEM);
    cudaFuncSetAttribute(chain_kernel, cudaFuncAttributeMaxDynamicSharedMemorySize, CH_SMEM);

    float* h   = (float*)p_h;
    float* hid = (float*)p_hid;
    int*   cnt = (int*)p_cnt;
    int*   rp  = (int*)p_rp;
    int*   fil = (int*)p_fill;
    int*   col = (int*)p_col;

    // barriers + CSR counters
    cudaMemsetAsync(p_bars, 0, 2*sizeof(unsigned));
    cudaMemsetAsync(p_cnt,  0, (size_t)LEVE*PP*sizeof(int));
    csr_count<<<512, 256>>>(src, cnt);
    csr_scan <<<LEVE, 256>>>(cnt, rp, fil);
    csr_fill <<<512, 256>>>(src, fil, col);

    // node transform
    ntgemm<0><<<NN/128, 256, NT_SMEM>>>(x,   nt_w1, nt_b1, hid);
    ntgemm<1><<<NN/128, 256, NT_SMEM>>>(hid, nt_w2, nt_b2, h);

    // both message-passing chains in one persistent kernel
    chain_kernel<<<2*CH, 256, CH_SMEM>>>(out, src,
        f_pre_w, f_pre_b, f_upd_w, f_upd_b,
        b_pre_w, b_pre_b, b_upd_w, b_upd_b);
}

// round 5
// speedup vs baseline: 3.0153x; 1.3725x over previous
#include <cuda_runtime.h>
#include <cstdint>

#define NN 131072
#define DD 128
#define LL 16
#define PP 8192
#define KK 8
#define PKE (PP*KK)
#define LEVE (LL-1)
#define CH 64            // CTAs per chain

// ---------------- scratch (static device globals; no allocation) ----------------
__device__ float g_h[(size_t)NN*DD];
__device__ float g_hid[(size_t)NN*DD];
__device__ float g_Mf[2*PP*DD];
__device__ float g_Mb[2*PP*DD];
__device__ int   g_cnt[LEVE*PP];
__device__ int   g_rp[LEVE*(PP+1)];
__device__ int   g_fill[LEVE*PP];
__device__ int   g_col[LEVE*PKE];
__device__ unsigned g_bars[2];

// W fragment layout size (see below)
#define A_FRAG_SZ (4*16*132)          // 8448 words
#define W_FRAG_SZ (16*16*66)          // 16896 words
__device__ unsigned g_wf[6*W_FRAG_SZ];   // 0 f_pre, 1 f_upd, 2 b_pre, 3 b_upd, 4 nt_w1, 5 nt_w2

// ---------------- tf32 / mma helpers ----------------
__device__ __forceinline__ unsigned tf32c(float f) {
    unsigned r;
    asm("cvt.rna.tf32.f32 %0, %1;" : "=r"(r) : "f"(f));
    return r;
}
__device__ __forceinline__ void mma8(float* d, const unsigned* a, const unsigned* b) {
    asm("mma.sync.aligned.m16n8k8.row.col.f32.tf32.tf32.f32 "
        "{%0,%1,%2,%3},{%4,%5,%6,%7},{%8,%9},{%0,%1,%2,%3};"
        : "+f"(d[0]), "+f"(d[1]), "+f"(d[2]), "+f"(d[3])
        : "r"(a[0]), "r"(a[1]), "r"(a[2]), "r"(a[3]), "r"(b[0]), "r"(b[1]));
}

// A tile: 64 rows x 128 k. Blocks (mb, kb), 132-word pitch.
// slot(r,k) = (r&7)*16 + (k&3)*4 + ((k>>2)&1)*2 + ((r>>3)&1)   (2-way staging conflicts only)
__device__ __forceinline__ void frag_storeA(unsigned* sA, int r, int c4, float4 v) {
    unsigned* p = sA + (((r>>4)*16 + (c4>>1))*132) + ((r&7)*16) + ((c4&1)*2) + ((r&15)>>3);
    p[0] = tf32c(v.x); p[4] = tf32c(v.y); p[8] = tf32c(v.z); p[12] = tf32c(v.w);
}

// ---------------- build W fragments once in GMEM (conflicts irrelevant there) ----------------
__global__ void build_wfrag(const float* w0, const float* w1, const float* w2,
                            const float* w3, const float* w4, const float* w5) {
    const float* W;
    switch (blockIdx.x) {
        case 0: W = w0; break; case 1: W = w1; break; case 2: W = w2; break;
        case 3: W = w3; break; case 4: W = w4; break; default: W = w5; break;
    }
    unsigned* dst = g_wf + (size_t)blockIdx.x * W_FRAG_SZ;
    const int tid = threadIdx.x;
    #pragma unroll
    for (int it = 0; it < 16; ++it) {
        const int idx = tid + 256*it;
        const int k = idx >> 5, c4 = idx & 31;
        const float4 v = ((const float4*)W)[idx];
        unsigned* p = dst + (((c4>>1)*16 + (k>>3))*66) + ((c4&1)*32) + ((k&3)*2) + ((k>>2)&1);
        p[0] = tf32c(v.x); p[8] = tf32c(v.y); p[16] = tf32c(v.z); p[24] = tf32c(v.w);
    }
}

// ---------------- GEMM core: 64x128 tile, 8 warps (wm in [0,2), wn in [0,4)) ----------------
__device__ __forceinline__ void gemm_core(const unsigned* __restrict__ sA,
                                          const unsigned* __restrict__ sW,
                                          int wm, int wn, int lane,
                                          float acc[2][4][4]) {
    #pragma unroll
    for (int i = 0; i < 2; ++i)
        #pragma unroll
        for (int j = 0; j < 4; ++j)
            #pragma unroll
            for (int q = 0; q < 4; ++q) acc[i][j][q] = 0.f;
    #pragma unroll
    for (int kb = 0; kb < 16; ++kb) {
        unsigned a[2][4];
        #pragma unroll
        for (int i = 0; i < 2; ++i) {
            const uint4 v = *(const uint4*)(sA + (((wm*2+i)*16 + kb)*132) + lane*4);
            a[i][0] = v.x; a[i][1] = v.y; a[i][2] = v.z; a[i][3] = v.w;
        }
        unsigned b[4][2];
        #pragma unroll
        for (int j = 0; j < 4; ++j) {
            const uint2 v = *(const uint2*)(sW + (((wn*4+j)*16 + kb)*66) + lane*2);
            b[j][0] = v.x; b[j][1] = v.y;
        }
        #pragma unroll
        for (int i = 0; i < 2; ++i)
            #pragma unroll
            for (int j = 0; j < 4; ++j)
                mma8(acc[i][j], a[i], b[j]);
    }
}

// ---------------- node transform GEMM ----------------
#define NT_SMEM ((W_FRAG_SZ + A_FRAG_SZ + 128) * 4)

template<int EPI>
__global__ __launch_bounds__(256, 2) void ntgemm(
    const float* __restrict__ A, const unsigned* __restrict__ wfrag,
    const float* __restrict__ bias, float* __restrict__ Out)
{
    extern __shared__ unsigned sm[];
    unsigned* sW = sm;
    unsigned* sA = sm + W_FRAG_SZ;
    float*    sB = (float*)(sm + W_FRAG_SZ + A_FRAG_SZ);
    const int tid = threadIdx.x, lane = tid & 31, w = tid >> 5;
    const int wm = w >> 2, wn = w & 3;
    const int g = lane >> 2, t = lane & 3;
    const int r0 = blockIdx.x * 128;

    // linear, conflict-free copy of pre-swizzled W
    for (int i = tid; i < W_FRAG_SZ/4; i += 256)
        ((uint4*)sW)[i] = ((const uint4*)wfrag)[i];
    if (tid < 32) ((float4*)sB)[tid] = ((const float4*)bias)[tid];
    __syncthreads();

    for (int sub = 0; sub < 2; ++sub) {
        #pragma unroll
        for (int it = 0; it < 8; ++it) {
            const int idx = tid + 256*it;
            const int r = idx >> 5, c4 = idx & 31;
            frag_storeA(sA, r, c4,
                *(const float4*)(A + (size_t)(r0 + sub*64 + r)*128 + c4*4));
        }
        __syncthreads();
        float acc[2][4][4];
        gemm_core(sA, sW, wm, wn, lane, acc);
        #pragma unroll
        for (int i = 0; i < 2; ++i) {
            const int rl = r0 + sub*64 + wm*32 + i*16 + g;
            #pragma unroll
            for (int j = 0; j < 4; ++j) {
                const int c = wn*32 + j*8 + t*2;
                const float b0 = sB[c], b1 = sB[c+1];
                float v0 = acc[i][j][0]+b0, v1 = acc[i][j][1]+b1;
                float v2 = acc[i][j][2]+b0, v3 = acc[i][j][3]+b1;
                if (EPI == 0) {
                    v0 = fmaxf(v0,0.f); v1 = fmaxf(v1,0.f);
                    v2 = fmaxf(v2,0.f); v3 = fmaxf(v3,0.f);
                }
                *(float2*)(Out + (size_t)rl*128 + c)     = make_float2(v0,v1);
                *(float2*)(Out + (size_t)(rl+8)*128 + c) = make_float2(v2,v3);
            }
        }
        __syncthreads();
    }
}

// ---------------- grid sync ----------------
__device__ __forceinline__ void gsync(unsigned* ctr, unsigned tgt) {
    __syncthreads();
    __threadfence();
    if (threadIdx.x == 0) {
        atomicAdd(ctr, 1u);
        while (*(volatile unsigned*)ctr < tgt) __nanosleep(64);
    }
    __syncthreads();
    __threadfence();
}

// ---------------- persistent dual-chain message-passing kernel (512 threads) ----------------
#define CH_SMEM ((2*W_FRAG_SZ + 2*A_FRAG_SZ + 256) * 4)

__global__ __launch_bounds__(512, 1) void chain_kernel(
    float* __restrict__ out,
    const int* __restrict__ src,
    const float* __restrict__ f_pre_b, const float* __restrict__ f_upd_b,
    const float* __restrict__ b_pre_b, const float* __restrict__ b_upd_b)
{
    extern __shared__ unsigned sm[];
    unsigned* sWpre = sm;
    unsigned* sWupd = sm + W_FRAG_SZ;
    unsigned* sA0   = sm + 2*W_FRAG_SZ;
    unsigned* sA1   = sA0 + A_FRAG_SZ;
    float*    sB    = (float*)(sA1 + A_FRAG_SZ);   // [0,128) pre_b, [128,256) upd_b

    const int tid = threadIdx.x, lane = tid & 31, w = tid >> 5;
    const int wg = w >> 3;              // warp-group 0/1 -> 64-row sub-tile
    const int wm = (w >> 2) & 1, wn = w & 3;
    const int g = lane >> 2, t = lane & 3;
    const bool fwd = blockIdx.x < CH;
    const int cc = fwd ? blockIdx.x : blockIdx.x - CH;
    const int r0 = cc * 128;
    const int cofs = fwd ? 0 : 128;
    unsigned* ctr = &g_bars[fwd ? 0 : 1];
    float* Mbase = fwd ? g_Mf : g_Mb;
    const unsigned* wfpre = g_wf + (size_t)(fwd ? 0 : 2) * W_FRAG_SZ;
    const unsigned* wfupd = g_wf + (size_t)(fwd ? 1 : 3) * W_FRAG_SZ;
    const float* preB = fwd ? f_pre_b : b_pre_b;
    const float* updB = fwd ? f_upd_b : b_upd_b;
    unsigned* sAw = wg ? sA1 : sA0;

    // linear copy of pre-swizzled weights
    for (int i = tid; i < W_FRAG_SZ/4; i += 512) {
        ((uint4*)sWpre)[i] = ((const uint4*)wfpre)[i];
        ((uint4*)sWupd)[i] = ((const uint4*)wfupd)[i];
    }
    if (tid < 32) {
        ((float4*)sB)[tid]       = ((const float4*)preB)[tid];
        ((float4*)(sB+128))[tid] = ((const float4*)updB)[tid];
    }
    __syncthreads();

    // boundary level: y = relu(upd_b) + h
    {
        const int lvl0 = fwd ? 0 : LEVE;
        #pragma unroll
        for (int it = 0; it < 8; ++it) {
            const int idx = tid + 512*it;               // 128 rows x 32 c4
            const int r = idx >> 5, c4 = idx & 31;
            const size_t node = (size_t)lvl0*PP + r0 + r;
            const float4 ub = *(const float4*)(sB + 128 + c4*4);
            const float4 hv = *(const float4*)(g_h + node*128 + c4*4);
            float4 o;
            o.x = fmaxf(ub.x,0.f)+hv.x; o.y = fmaxf(ub.y,0.f)+hv.y;
            o.z = fmaxf(ub.z,0.f)+hv.z; o.w = fmaxf(ub.w,0.f)+hv.w;
            *(float4*)(out + node*256 + cofs + c4*4) = o;
        }
    }
    __syncthreads();

    unsigned tgt = 0;
    for (int step = 0; step < LEVE; ++step) {
        const int l    = fwd ? (1+step) : (LEVE-1-step);
        const int ylvl = fwd ? (l-1)    : (l+1);
        float* Mbuf = Mbase + (size_t)(l & 1)*PP*DD;

        // ---- phase A: M[p] = relu(Y[ylvl][p] @ preW + preB), own 128 rows ----
        #pragma unroll
        for (int it = 0; it < 8; ++it) {
            const int idx = tid + 512*it;               // 4096 float4
            const int r = idx >> 5, c4 = idx & 31;
            frag_storeA((r < 64) ? sA0 : sA1, r & 63, c4,
                *(const float4*)(out + ((size_t)ylvl*PP + r0 + r)*256 + cofs + c4*4));
        }
        __syncthreads();
        {
            float acc[2][4][4];
            gemm_core(sAw, sWpre, wm, wn, lane, acc);
            #pragma unroll
            for (int i = 0; i < 2; ++i) {
                const int rl = r0 + wg*64 + wm*32 + i*16 + g;
                #pragma unroll
                for (int j = 0; j < 4; ++j) {
                    const int c = wn*32 + j*8 + t*2;
                    const float b0 = sB[c], b1 = sB[c+1];
                    const float v0 = fmaxf(acc[i][j][0]+b0, 0.f);
                    const float v1 = fmaxf(acc[i][j][1]+b1, 0.f);
                    const float v2 = fmaxf(acc[i][j][2]+b0, 0.f);
                    const float v3 = fmaxf(acc[i][j][3]+b1, 0.f);
                    *(float2*)(Mbuf + (size_t)rl*128 + c)     = make_float2(v0,v1);
                    *(float2*)(Mbuf + (size_t)(rl+8)*128 + c) = make_float2(v2,v3);
                }
            }
        }

        // ---- chain-wide barrier: all M writes visible ----
        tgt += CH;
        gsync(ctr, tgt);

        // ---- phase B: z = gather-mean(M); Y[l] = relu(z @ updW + updB) + h ----
        #pragma unroll 1
        for (int it = 0; it < 8; ++it) {
            const int idx = tid + 512*it;
            const int r = idx >> 5, c4 = idx & 31;
            const int pl = r0 + r;
            float4 v = make_float4(0.f,0.f,0.f,0.f);
            if (fwd) {
                const int* s = src + (size_t)(l-1)*PKE + pl*KK;
                #pragma unroll
                for (int k = 0; k < KK; ++k) {
                    const float4 m = *(const float4*)(Mbuf + (size_t)s[k]*128 + c4*4);
                    v.x += m.x; v.y += m.y; v.z += m.z; v.w += m.w;
                }
                v.x *= 0.125f; v.y *= 0.125f; v.z *= 0.125f; v.w *= 0.125f;
            } else {
                const int* rpl = g_rp + l*(PP+1);
                const int b0 = rpl[pl], e0 = rpl[pl+1];
                const int* colsl = g_col + (size_t)l*PKE;
                for (int jj = b0; jj < e0; ++jj) {
                    const float4 m = *(const float4*)(Mbuf + (size_t)colsl[jj]*128 + c4*4);
                    v.x += m.x; v.y += m.y; v.z += m.z; v.w += m.w;
                }
                if (e0 > b0) {
                    const float inv = 1.0f/(float)(e0-b0);
                    v.x *= inv; v.y *= inv; v.z *= inv; v.w *= inv;
                }
            }
            frag_storeA((r < 64) ? sA0 : sA1, r & 63, c4, v);
        }
        __syncthreads();
        {
            float acc[2][4][4];
            gemm_core(sAw, sWupd, wm, wn, lane, acc);
            #pragma unroll
            for (int i = 0; i < 2; ++i) {
                const int rl = r0 + wg*64 + wm*32 + i*16 + g;
                #pragma unroll
                for (int j = 0; j < 4; ++j) {
                    const int c = wn*32 + j*8 + t*2;
                    const float b0 = sB[128+c], b1 = sB[128+c+1];
                    float v0 = fmaxf(acc[i][j][0]+b0, 0.f);
                    float v1 = fmaxf(acc[i][j][1]+b1, 0.f);
                    float v2 = fmaxf(acc[i][j][2]+b0, 0.f);
                    float v3 = fmaxf(acc[i][j][3]+b1, 0.f);
                    const size_t nlo = (size_t)l*PP + rl, nhi = nlo + 8;
                    const float2 hlo = *(const float2*)(g_h + nlo*128 + c);
                    const float2 hhi = *(const float2*)(g_h + nhi*128 + c);
                    v0 += hlo.x; v1 += hlo.y; v2 += hhi.x; v3 += hhi.y;
                    *(float2*)(out + nlo*256 + cofs + c) = make_float2(v0,v1);
                    *(float2*)(out + nhi*256 + cofs + c) = make_float2(v2,v3);
                }
            }
        }
        __syncthreads();   // protect sA before next level's staging
    }
}

// ---------------- CSR build for reverse direction ----------------
__global__ void csr_count(const int* __restrict__ src, int* __restrict__ cnt) {
    const int tot = LEVE*PKE;
    for (int e = blockIdx.x*blockDim.x + threadIdx.x; e < tot; e += gridDim.x*blockDim.x)
        atomicAdd(&cnt[(e >> 16)*PP + src[e]], 1);
}
__global__ void csr_scan(const int* __restrict__ cnt, int* __restrict__ rp, int* __restrict__ fill) {
    const int lvl = blockIdx.x;
    const int t = threadIdx.x;
    const int base = lvl*PP;
    int c[32]; int sum = 0;
    #pragma unroll
    for (int j = 0; j < 32; ++j) { c[j] = cnt[base + t*32 + j]; sum += c[j]; }
    __shared__ int sh[256];
    sh[t] = sum; __syncthreads();
    for (int d = 1; d < 256; d <<= 1) {
        int v = (t >= d) ? sh[t-d] : 0;
        __syncthreads();
        sh[t] += v;
        __syncthreads();
    }
    int off = sh[t] - sum;
    int* rpl = rp + lvl*(PP+1);
    int* fl  = fill + base;
    #pragma unroll
    for (int j = 0; j < 32; ++j) { const int idx = t*32 + j; rpl[idx] = off; fl[idx] = off; off += c[j]; }
    if (t == 255) rpl[PP] = off;
}
__global__ void csr_fill(const int* __restrict__ src, int* __restrict__ fill, int* __restrict__ col) {
    const int tot = LEVE*PKE;
    for (int e = blockIdx.x*blockDim.x + threadIdx.x; e < tot; e += gridDim.x*blockDim.x) {
        const int lvl = e >> 16;
        const int le  = e & (PKE-1);
        const int pos = atomicAdd(&fill[lvl*PP + src[e]], 1);
        col[(size_t)lvl*PKE + pos] = le >> 3;
    }
}

// ---------------- launch ----------------
extern "C" void kernel_launch(void* const* d_in, const int* in_sizes, int n_in,
                              void* d_out, int out_size) {
    const float* x       = (const float*)d_in[0];
    const int*   src     = (const int*)  d_in[1];
    const float* nt_w1   = (const float*)d_in[2];
    const float* nt_b1   = (const float*)d_in[3];
    const float* nt_w2   = (const float*)d_in[4];
    const float* nt_b2   = (const float*)d_in[5];
    const float* f_pre_w = (const float*)d_in[6];
    const float* f_pre_b = (const float*)d_in[7];
    const float* f_upd_w = (const float*)d_in[8];
    const float* f_upd_b = (const float*)d_in[9];
    const float* b_pre_w = (const float*)d_in[10];
    const float* b_pre_b = (const float*)d_in[11];
    const float* b_upd_w = (const float*)d_in[12];
    const float* b_upd_b = (const float*)d_in[13];
    float* out = (float*)d_out;

    void *p_h, *p_hid, *p_cnt, *p_rp, *p_fill, *p_col, *p_bars, *p_wf;
    cudaGetSymbolAddress(&p_h,   g_h);
    cudaGetSymbolAddress(&p_hid, g_hid);
    cudaGetSymbolAddress(&p_cnt, g_cnt);
    cudaGetSymbolAddress(&p_rp,  g_rp);
    cudaGetSymbolAddress(&p_fill,g_fill);
    cudaGetSymbolAddress(&p_col, g_col);
    cudaGetSymbolAddress(&p_bars,g_bars);
    cudaGetSymbolAddress(&p_wf,  g_wf);

    cudaFuncSetAttribute(ntgemm<0>,    cudaFuncAttributeMaxDynamicSharedMemorySize, NT_SMEM);
    cudaFuncSetAttribute(ntgemm<1>,    cudaFuncAttributeMaxDynamicSharedMemorySize, NT_SMEM);
    cudaFuncSetAttribute(chain_kernel, cudaFuncAttributeMaxDynamicSharedMemorySize, CH_SMEM);

    float* h   = (float*)p_h;
    float* hid = (float*)p_hid;
    int*   cnt = (int*)p_cnt;
    int*   rp  = (int*)p_rp;
    int*   fil = (int*)p_fill;
    int*   col = (int*)p_col;
    unsigned* wf = (unsigned*)p_wf;

    // W fragments + barriers + CSR
    build_wfrag<<<6, 256>>>(f_pre_w, f_upd_w, b_pre_w, b_upd_w, nt_w1, nt_w2);
    cudaMemsetAsync(p_bars, 0, 2*sizeof(unsigned));
    cudaMemsetAsync(p_cnt,  0, (size_t)LEVE*PP*sizeof(int));
    csr_count<<<512, 256>>>(src, cnt);
    csr_scan <<<LEVE, 256>>>(cnt, rp, fil);
    csr_fill <<<512, 256>>>(src, fil, col);

    // node transform
    ntgemm<0><<<NN/128, 256, NT_SMEM>>>(x,   wf + (size_t)4*W_FRAG_SZ, nt_b1, hid);
    ntgemm<1><<<NN/128, 256, NT_SMEM>>>(hid, wf + (size_t)5*W_FRAG_SZ, nt_b2, h);

    // both message-passing chains in one persistent kernel
    chain_kernel<<<2*CH, 512, CH_SMEM>>>(out, src,
        f_pre_b, f_upd_b, b_pre_b, b_upd_b);
}

// round 6
// speedup vs baseline: 3.1078x; 1.0307x over previous
#include <cuda_runtime.h>
#include <cuda_fp16.h>
#include <cstdint>

#define NN 131072
#define DD 128
#define LL 16
#define PP 8192
#define KK 8
#define PKE (PP*KK)
#define LEVE (LL-1)
#define CH 64            // CTAs per chain
#define NTB (NN/128)     // 1024 gemm blocks in NT kernels

// ---------------- scratch (static device globals; no allocation) ----------------
__device__ float  g_h[(size_t)NN*DD];
__device__ float  g_hid[(size_t)NN*DD];
__device__ __half g_Mf[2*PP*DD];
__device__ __half g_Mb[2*PP*DD];
__device__ int    g_cnt[LEVE*PP];
__device__ int    g_rp[LEVE*(PP+1)];
__device__ int    g_fill[LEVE*PP];
__device__ int    g_col[LEVE*PKE];
__device__ unsigned g_bars[2];

#define A_FRAG_SZ (4*16*132)          // 8448 words
#define W_FRAG_SZ (16*16*66)          // 16896 words
__device__ unsigned g_wf[6*W_FRAG_SZ];   // 0 f_pre, 1 f_upd, 2 b_pre, 3 b_upd, 4 nt_w1, 5 nt_w2

// ---------------- tf32 / mma helpers ----------------
__device__ __forceinline__ unsigned tf32c(float f) {
    unsigned r;
    asm("cvt.rna.tf32.f32 %0, %1;" : "=r"(r) : "f"(f));
    return r;
}
__device__ __forceinline__ void mma8(float* d, const unsigned* a, const unsigned* b) {
    asm("mma.sync.aligned.m16n8k8.row.col.f32.tf32.tf32.f32 "
        "{%0,%1,%2,%3},{%4,%5,%6,%7},{%8,%9},{%0,%1,%2,%3};"
        : "+f"(d[0]), "+f"(d[1]), "+f"(d[2]), "+f"(d[3])
        : "r"(a[0]), "r"(a[1]), "r"(a[2]), "r"(a[3]), "r"(b[0]), "r"(b[1]));
}

__device__ __forceinline__ void frag_storeA(unsigned* sA, int r, int c4, float4 v) {
    unsigned* p = sA + (((r>>4)*16 + (c4>>1))*132) + ((r&7)*16) + ((c4&1)*2) + ((r&15)>>3);
    p[0] = tf32c(v.x); p[4] = tf32c(v.y); p[8] = tf32c(v.z); p[12] = tf32c(v.w);
}

// ---------------- build W fragments once + zero counters/barriers ----------------
__global__ void build_wfrag(const float* w0, const float* w1, const float* w2,
                            const float* w3, const float* w4, const float* w5) {
    const float* W;
    switch (blockIdx.x) {
        case 0: W = w0; break; case 1: W = w1; break; case 2: W = w2; break;
        case 3: W = w3; break; case 4: W = w4; break; default: W = w5; break;
    }
    unsigned* dst = g_wf + (size_t)blockIdx.x * W_FRAG_SZ;
    const int tid = threadIdx.x;
    #pragma unroll
    for (int it = 0; it < 16; ++it) {
        const int idx = tid + 256*it;
        const int k = idx >> 5, c4 = idx & 31;
        const float4 v = ((const float4*)W)[idx];
        unsigned* p = dst + (((c4>>1)*16 + (k>>3))*66) + ((c4&1)*32) + ((k&3)*2) + ((k>>2)&1);
        p[0] = tf32c(v.x); p[8] = tf32c(v.y); p[16] = tf32c(v.z); p[24] = tf32c(v.w);
    }
    // zero CSR counters + grid barriers (replaces two memsets)
    for (int i = blockIdx.x*256 + tid; i < LEVE*PP; i += 6*256) g_cnt[i] = 0;
    if (blockIdx.x == 0 && tid < 2) g_bars[tid] = 0;
}

// ---------------- GEMM core: 64x128 tile, 8 warps (wm in [0,2), wn in [0,4)) ----------------
__device__ __forceinline__ void gemm_core(const unsigned* __restrict__ sA,
                                          const unsigned* __restrict__ sW,
                                          int wm, int wn, int lane,
                                          float acc[2][4][4]) {
    #pragma unroll
    for (int i = 0; i < 2; ++i)
        #pragma unroll
        for (int j = 0; j < 4; ++j)
            #pragma unroll
            for (int q = 0; q < 4; ++q) acc[i][j][q] = 0.f;
    #pragma unroll
    for (int kb = 0; kb < 16; ++kb) {
        unsigned a[2][4];
        #pragma unroll
        for (int i = 0; i < 2; ++i) {
            const uint4 v = *(const uint4*)(sA + (((wm*2+i)*16 + kb)*132) + lane*4);
            a[i][0] = v.x; a[i][1] = v.y; a[i][2] = v.z; a[i][3] = v.w;
        }
        unsigned b[4][2];
        #pragma unroll
        for (int j = 0; j < 4; ++j) {
            const uint2 v = *(const uint2*)(sW + (((wn*4+j)*16 + kb)*66) + lane*2);
            b[j][0] = v.x; b[j][1] = v.y;
        }
        #pragma unroll
        for (int i = 0; i < 2; ++i)
            #pragma unroll
            for (int j = 0; j < 4; ++j)
                mma8(acc[i][j], a[i], b[j]);
    }
}

// ---------------- node transform GEMM (+ piggybacked CSR work) ----------------
// EXTRA 1: blocks >= NTB do csr_count.   EXTRA 2: blocks >= NTB do csr_scan.
#define NT_SMEM ((W_FRAG_SZ + A_FRAG_SZ + 128) * 4)

template<int EPI, int EXTRA>
__global__ __launch_bounds__(256, 2) void ntgemm(
    const float* __restrict__ A, const unsigned* __restrict__ wfrag,
    const float* __restrict__ bias, float* __restrict__ Out,
    const int* __restrict__ src)
{
    extern __shared__ unsigned sm[];
    const int tid = threadIdx.x;

    if (EXTRA == 1 && blockIdx.x >= NTB) {
        const int b = blockIdx.x - NTB;          // 64 count blocks
        const int tot = LEVE*PKE;
        for (int e = b*256 + tid; e < tot; e += 64*256)
            atomicAdd(&g_cnt[(e >> 16)*PP + src[e]], 1);
        return;
    }
    if (EXTRA == 2 && blockIdx.x >= NTB) {
        const int lvl = blockIdx.x - NTB;        // 15 scan blocks
        const int base = lvl*PP;
        int c[32]; int sum = 0;
        #pragma unroll
        for (int j = 0; j < 32; ++j) { c[j] = g_cnt[base + tid*32 + j]; sum += c[j]; }
        int* sh = (int*)sm;
        sh[tid] = sum; __syncthreads();
        for (int d = 1; d < 256; d <<= 1) {
            int v = (tid >= d) ? sh[tid-d] : 0;
            __syncthreads();
            sh[tid] += v;
            __syncthreads();
        }
        int off = sh[tid] - sum;
        int* rpl = g_rp + lvl*(PP+1);
        #pragma unroll
        for (int j = 0; j < 32; ++j) {
            const int idx = tid*32 + j;
            rpl[idx] = off; g_fill[base + idx] = off; off += c[j];
        }
        if (tid == 255) rpl[PP] = off;
        return;
    }

    unsigned* sW = sm;
    unsigned* sA = sm + W_FRAG_SZ;
    float*    sB = (float*)(sm + W_FRAG_SZ + A_FRAG_SZ);
    const int lane = tid & 31, w = tid >> 5;
    const int wm = w >> 2, wn = w & 3;
    const int g = lane >> 2, t = lane & 3;
    const int r0 = blockIdx.x * 128;

    for (int i = tid; i < W_FRAG_SZ/4; i += 256)
        ((uint4*)sW)[i] = ((const uint4*)wfrag)[i];
    if (tid < 32) ((float4*)sB)[tid] = ((const float4*)bias)[tid];
    __syncthreads();

    for (int sub = 0; sub < 2; ++sub) {
        #pragma unroll
        for (int it = 0; it < 8; ++it) {
            const int idx = tid + 256*it;
            const int r = idx >> 5, c4 = idx & 31;
            frag_storeA(sA, r, c4,
                *(const float4*)(A + (size_t)(r0 + sub*64 + r)*128 + c4*4));
        }
        __syncthreads();
        float acc[2][4][4];
        gemm_core(sA, sW, wm, wn, lane, acc);
        #pragma unroll
        for (int i = 0; i < 2; ++i) {
            const int rl = r0 + sub*64 + wm*32 + i*16 + g;
            #pragma unroll
            for (int j = 0; j < 4; ++j) {
                const int c = wn*32 + j*8 + t*2;
                const float b0 = sB[c], b1 = sB[c+1];
                float v0 = acc[i][j][0]+b0, v1 = acc[i][j][1]+b1;
                float v2 = acc[i][j][2]+b0, v3 = acc[i][j][3]+b1;
                if (EPI == 0) {
                    v0 = fmaxf(v0,0.f); v1 = fmaxf(v1,0.f);
                    v2 = fmaxf(v2,0.f); v3 = fmaxf(v3,0.f);
                }
                *(float2*)(Out + (size_t)rl*128 + c)     = make_float2(v0,v1);
                *(float2*)(Out + (size_t)(rl+8)*128 + c) = make_float2(v2,v3);
            }
        }
        __syncthreads();
    }
}

// ---------------- grid sync ----------------
__device__ __forceinline__ void gsync(unsigned* ctr, unsigned tgt) {
    __syncthreads();
    __threadfence();
    if (threadIdx.x == 0) {
        atomicAdd(ctr, 1u);
        while (*(volatile unsigned*)ctr < tgt) __nanosleep(64);
    }
    __syncthreads();
    __threadfence();
}
#define WG_BAR() asm volatile("bar.sync %0, 256;" :: "r"(1+wg) : "memory")

// ---------------- persistent dual-chain message-passing kernel (512 threads) ----------------
#define CH_SMEM ((2*W_FRAG_SZ + 2*A_FRAG_SZ + 256) * 4)

__global__ __launch_bounds__(512, 1) void chain_kernel(
    float* __restrict__ out,
    const int* __restrict__ src,
    const float* __restrict__ f_pre_b, const float* __restrict__ f_upd_b,
    const float* __restrict__ b_pre_b, const float* __restrict__ b_upd_b)
{
    extern __shared__ unsigned sm[];
    unsigned* sWpre = sm;
    unsigned* sWupd = sm + W_FRAG_SZ;
    unsigned* sA0   = sm + 2*W_FRAG_SZ;
    unsigned* sA1   = sA0 + A_FRAG_SZ;
    float*    sB    = (float*)(sA1 + A_FRAG_SZ);   // [0,128) pre_b, [128,256) upd_b

    const int tid = threadIdx.x, lane = tid & 31, w = tid >> 5;
    const int wg = w >> 3;              // warp-group 0/1 owns 64-row sub-tile
    const int lt = tid & 255;           // tid within warp-group
    const int wm = (w >> 2) & 1, wn = w & 3;
    const int g = lane >> 2, t = lane & 3;
    const bool fwd = blockIdx.x < CH;
    const int cc = fwd ? blockIdx.x : blockIdx.x - CH;
    const int r0 = cc * 128;
    const int cofs = fwd ? 0 : 128;
    unsigned* ctr = &g_bars[fwd ? 0 : 1];
    __half* Mbase = fwd ? g_Mf : g_Mb;
    const unsigned* wfpre = g_wf + (size_t)(fwd ? 0 : 2) * W_FRAG_SZ;
    const unsigned* wfupd = g_wf + (size_t)(fwd ? 1 : 3) * W_FRAG_SZ;
    const float* preB = fwd ? f_pre_b : b_pre_b;
    const float* updB = fwd ? f_upd_b : b_upd_b;
    unsigned* sAw = wg ? sA1 : sA0;

    // reverse CTAs build the CSR col/fill (scan finished in ntgemm<1>);
    // publication to other CTAs is via the release fence in the first gsync.
    if (!fwd) {
        const int tot = LEVE*PKE;
        for (int e = cc*512 + tid; e < tot; e += CH*512) {
            const int lvl = e >> 16;
            const int le  = e & (PKE-1);
            const int pos = atomicAdd(&g_fill[lvl*PP + src[e]], 1);
            g_col[(size_t)lvl*PKE + pos] = le >> 3;
        }
    }

    for (int i = tid; i < W_FRAG_SZ/4; i += 512) {
        ((uint4*)sWpre)[i] = ((const uint4*)wfpre)[i];
        ((uint4*)sWupd)[i] = ((const uint4*)wfupd)[i];
    }
    if (tid < 32) {
        ((float4*)sB)[tid]       = ((const float4*)preB)[tid];
        ((float4*)(sB+128))[tid] = ((const float4*)updB)[tid];
    }
    __syncthreads();

    // boundary level: y = relu(upd_b) + h
    {
        const int lvl0 = fwd ? 0 : LEVE;
        #pragma unroll
        for (int it = 0; it < 8; ++it) {
            const int idx = tid + 512*it;
            const int r = idx >> 5, c4 = idx & 31;
            const size_t node = (size_t)lvl0*PP + r0 + r;
            const float4 ub = *(const float4*)(sB + 128 + c4*4);
            const float4 hv = *(const float4*)(g_h + node*128 + c4*4);
            float4 o;
            o.x = fmaxf(ub.x,0.f)+hv.x; o.y = fmaxf(ub.y,0.f)+hv.y;
            o.z = fmaxf(ub.z,0.f)+hv.z; o.w = fmaxf(ub.w,0.f)+hv.w;
            *(float4*)(out + node*256 + cofs + c4*4) = o;
        }
    }
    __syncthreads();

    unsigned tgt = 0;
    for (int step = 0; step < LEVE; ++step) {
        const int l    = fwd ? (1+step) : (LEVE-1-step);
        const int ylvl = fwd ? (l-1)    : (l+1);
        __half* Mbuf = Mbase + (size_t)(l & 1)*PP*DD;

        // ---- phase A: M[p] = relu(Y[ylvl][p] @ preW + preB), wg's own 64 rows ----
        #pragma unroll
        for (int it = 0; it < 8; ++it) {
            const int idx = lt + 256*it;                 // 64 rows x 32 c4
            const int r = idx >> 5, c4 = idx & 31;
            frag_storeA(sAw, r, c4,
                *(const float4*)(out + ((size_t)ylvl*PP + r0 + wg*64 + r)*256 + cofs + c4*4));
        }
        WG_BAR();
        {
            float acc[2][4][4];
            gemm_core(sAw, sWpre, wm, wn, lane, acc);
            #pragma unroll
            for (int i = 0; i < 2; ++i) {
                const int rl = r0 + wg*64 + wm*32 + i*16 + g;
                #pragma unroll
                for (int j = 0; j < 4; ++j) {
                    const int c = wn*32 + j*8 + t*2;
                    const float b0 = sB[c], b1 = sB[c+1];
                    const float v0 = fmaxf(acc[i][j][0]+b0, 0.f);
                    const float v1 = fmaxf(acc[i][j][1]+b1, 0.f);
                    const float v2 = fmaxf(acc[i][j][2]+b0, 0.f);
                    const float v3 = fmaxf(acc[i][j][3]+b1, 0.f);
                    *(__half2*)(Mbuf + (size_t)rl*128 + c)     = __floats2half2_rn(v0, v1);
                    *(__half2*)(Mbuf + (size_t)(rl+8)*128 + c) = __floats2half2_rn(v2, v3);
                }
            }
        }

        // ---- chain-wide barrier: all M writes visible ----
        tgt += CH;
        gsync(ctr, tgt);

        // ---- phase B: z = gather-mean(M); Y[l] = relu(z @ updW + updB) + h ----
        #pragma unroll 1
        for (int it = 0; it < 8; ++it) {
            const int idx = lt + 256*it;
            const int r = idx >> 5, c4 = idx & 31;
            const int pl = r0 + wg*64 + r;
            float4 v = make_float4(0.f,0.f,0.f,0.f);
            if (fwd) {
                const int* s = src + (size_t)(l-1)*PKE + pl*KK;
                #pragma unroll
                for (int k = 0; k < KK; ++k) {
                    const uint2 u = *(const uint2*)(Mbuf + (size_t)s[k]*128 + c4*4);
                    const float2 f0 = __half22float2(*(const __half2*)&u.x);
                    const float2 f1 = __half22float2(*(const __half2*)&u.y);
                    v.x += f0.x; v.y += f0.y; v.z += f1.x; v.w += f1.y;
                }
                v.x *= 0.125f; v.y *= 0.125f; v.z *= 0.125f; v.w *= 0.125f;
            } else {
                const int* rpl = g_rp + l*(PP+1);
                const int b0 = rpl[pl], e0 = rpl[pl+1];
                const int* colsl = g_col + (size_t)l*PKE;
                for (int jj = b0; jj < e0; ++jj) {
                    const uint2 u = *(const uint2*)(Mbuf + (size_t)colsl[jj]*128 + c4*4);
                    const float2 f0 = __half22float2(*(const __half2*)&u.x);
                    const float2 f1 = __half22float2(*(const __half2*)&u.y);
                    v.x += f0.x; v.y += f0.y; v.z += f1.x; v.w += f1.y;
                }
                if (e0 > b0) {
                    const float inv = 1.0f/(float)(e0-b0);
                    v.x *= inv; v.y *= inv; v.z *= inv; v.w *= inv;
                }
            }
            frag_storeA(sAw, r, c4, v);
        }
        WG_BAR();
        {
            float acc[2][4][4];
            gemm_core(sAw, sWupd, wm, wn, lane, acc);
            #pragma unroll
            for (int i = 0; i < 2; ++i) {
                const int rl = r0 + wg*64 + wm*32 + i*16 + g;
                #pragma unroll
                for (int j = 0; j < 4; ++j) {
                    const int c = wn*32 + j*8 + t*2;
                    const float b0 = sB[128+c], b1 = sB[128+c+1];
                    float v0 = fmaxf(acc[i][j][0]+b0, 0.f);
                    float v1 = fmaxf(acc[i][j][1]+b1, 0.f);
                    float v2 = fmaxf(acc[i][j][2]+b0, 0.f);
                    float v3 = fmaxf(acc[i][j][3]+b1, 0.f);
                    const size_t nlo = (size_t)l*PP + rl, nhi = nlo + 8;
                    const float2 hlo = *(const float2*)(g_h + nlo*128 + c);
                    const float2 hhi = *(const float2*)(g_h + nhi*128 + c);
                    v0 += hlo.x; v1 += hlo.y; v2 += hhi.x; v3 += hhi.y;
                    *(float2*)(out + nlo*256 + cofs + c) = make_float2(v0,v1);
                    *(float2*)(out + nhi*256 + cofs + c) = make_float2(v2,v3);
                }
            }
        }
        WG_BAR();   // protect sAw before next level's staging
    }
}

// ---------------- launch ----------------
extern "C" void kernel_launch(void* const* d_in, const int* in_sizes, int n_in,
                              void* d_out, int out_size) {
    const float* x       = (const float*)d_in[0];
    const int*   src     = (const int*)  d_in[1];
    const float* nt_w1   = (const float*)d_in[2];
    const float* nt_b1   = (const float*)d_in[3];
    const float* nt_w2   = (const float*)d_in[4];
    const float* nt_b2   = (const float*)d_in[5];
    const float* f_pre_w = (const float*)d_in[6];
    const float* f_pre_b = (const float*)d_in[7];
    const float* f_upd_w = (const float*)d_in[8];
    const float* f_upd_b = (const float*)d_in[9];
    const float* b_pre_w = (const float*)d_in[10];
    const float* b_pre_b = (const float*)d_in[11];
    const float* b_upd_w = (const float*)d_in[12];
    const float* b_upd_b = (const float*)d_in[13];
    float* out = (float*)d_out;

    void *p_h, *p_hid, *p_wf;
    cudaGetSymbolAddress(&p_h,   g_h);
    cudaGetSymbolAddress(&p_hid, g_hid);
    cudaGetSymbolAddress(&p_wf,  g_wf);

    cudaFuncSetAttribute(ntgemm<0,1>,  cudaFuncAttributeMaxDynamicSharedMemorySize, NT_SMEM);
    cudaFuncSetAttribute(ntgemm<1,2>,  cudaFuncAttributeMaxDynamicSharedMemorySize, NT_SMEM);
    cudaFuncSetAttribute(chain_kernel, cudaFuncAttributeMaxDynamicSharedMemorySize, CH_SMEM);

    float* h   = (float*)p_h;
    float* hid = (float*)p_hid;
    unsigned* wf = (unsigned*)p_wf;

    // 1) W fragments + zero counters/barriers
    build_wfrag<<<6, 256>>>(f_pre_w, f_upd_w, b_pre_w, b_upd_w, nt_w1, nt_w2);

    // 2) NT layer 1 (+ csr_count in 64 extra blocks)
    ntgemm<0,1><<<NTB + 64, 256, NT_SMEM>>>(x,   wf + (size_t)4*W_FRAG_SZ, nt_b1, hid, src);
    // 3) NT layer 2 (+ csr_scan in 15 extra blocks)
    ntgemm<1,2><<<NTB + LEVE, 256, NT_SMEM>>>(hid, wf + (size_t)5*W_FRAG_SZ, nt_b2, h, src);

    // 4) both message-passing chains (reverse CTAs do csr_fill at start)
    chain_kernel<<<2*CH, 512, CH_SMEM>>>(out, src,
        f_pre_b, f_upd_b, b_pre_b, b_upd_b);
}